// round 2
// baseline (speedup 1.0000x reference)
#include <cuda_runtime.h>

// MultiScaleProcessor: input [64,256,256,3] f32 -> output [64,4,256,256,3] f32
// scales = {32,64,128,256}; bilinear (linspace endpoints), zero-pad to 256.

#define HH 256
#define WW 256
#define NB 64
#define ROWF (WW * 3)        // 768 floats per row
#define ROWV (ROWF / 4)      // 192 float4 per row
#define CHUNK 8              // rows per block; all pads (112,96,64) are %8==0
#define CROWV (CHUNK * ROWV) // 1536 float4 per chunk
#define NT 256
#define VPT (CROWV / NT)     // 6 float4 per thread
#define PPT (CHUNK * WW / NT) // 8 pixels per thread (compute path)

__global__ __launch_bounds__(NT) void msp_kernel(const float* __restrict__ in,
                                                 float* __restrict__ out) {
    const int yc  = blockIdx.x * CHUNK;  // first output row of this chunk
    const int sc  = blockIdx.y;          // scale index
    const int b   = blockIdx.z;          // batch
    const int s   = 32 << sc;
    const int p   = (256 - s) >> 1;
    const int tid = threadIdx.x;

    float4* __restrict__ ochunk =
        (float4*)(out + ((((size_t)b * 4 + sc) * HH + yc) * ROWF));

    if (s == 256) {
        // native: straight 8-row copy, 6 x STG.128 per thread
        const float4* __restrict__ ichunk =
            (const float4*)(in + ((size_t)b * HH + yc) * ROWF);
#pragma unroll
        for (int i = 0; i < VPT; i++)
            ochunk[tid + i * NT] = ichunk[tid + i * NT];
        return;
    }

    if (yc + CHUNK <= p || yc >= p + s) {
        // fully padded chunk: 6 x STG.128 zeros per thread
        const float4 z = make_float4(0.f, 0.f, 0.f, 0.f);
#pragma unroll
        for (int i = 0; i < VPT; i++)
            ochunk[tid + i * NT] = z;
        return;
    }

    // compute chunk: bilinear 8 rows into shared, then vectorized flush
    __shared__ __align__(16) float rows[CHUNK * ROWF];

    const float inv = 255.0f / (float)(s - 1);
    const float* __restrict__ base = in + (size_t)b * (HH * ROWF);

#pragma unroll
    for (int i = 0; i < PPT; i++) {
        const int pi = tid + i * NT;       // 0..2047
        const int r  = pi >> 8;            // local row 0..7
        const int x  = pi & 255;           // column 0..255
        float* dst = &rows[r * ROWF + 3 * x];
        if (x < p || x >= p + s) {
            dst[0] = 0.f; dst[1] = 0.f; dst[2] = 0.f;
        } else {
            const int   y  = yc + r - p;   // source-scale row index
            const float fy = (float)y * inv;
            const int   y0 = (int)fy;      // fy >= 0, trunc == floor
            const int   y1 = min(y0 + 1, HH - 1);
            const float wy = fy - (float)y0;

            const float fx = (float)(x - p) * inv;
            const int   x0 = (int)fx;
            const int   x1 = min(x0 + 1, WW - 1);
            const float wx = fx - (float)x0;

            const float* __restrict__ r0 = base + (size_t)y0 * ROWF;
            const float* __restrict__ r1 = base + (size_t)y1 * ROWF;
            const float wx0 = 1.f - wx;
            const float wy0 = 1.f - wy;
#pragma unroll
            for (int c = 0; c < 3; c++) {
                const float t  = __ldg(r0 + 3 * x0 + c) * wx0 +
                                 __ldg(r0 + 3 * x1 + c) * wx;
                const float bt = __ldg(r1 + 3 * x0 + c) * wx0 +
                                 __ldg(r1 + 3 * x1 + c) * wx;
                dst[c] = t * wy0 + bt * wy;
            }
        }
    }
    __syncthreads();

    const float4* __restrict__ srow = (const float4*)rows;
#pragma unroll
    for (int i = 0; i < VPT; i++)
        ochunk[tid + i * NT] = srow[tid + i * NT];
}

extern "C" void kernel_launch(void* const* d_in, const int* in_sizes, int n_in,
                              void* d_out, int out_size) {
    const float* in  = (const float*)d_in[0];
    float*       out = (float*)d_out;
    (void)in_sizes; (void)n_in; (void)out_size;

    dim3 grid(HH / CHUNK, 4, NB);  // 32 x 4 x 64 = 8192 blocks
    msp_kernel<<<grid, NT>>>(in, out);
}